// round 11
// baseline (speedup 1.0000x reference)
#include <cuda_runtime.h>
#include <cuda_fp16.h>
#include <cstdint>

// Problem dims
#define BB 4
#define SS 2048
#define DD 1024
#define HH 16
#define WW 64
#define NEL (BB*HH*SS*WW)
#define GM 8192
#define GK 1024
#define GN 3072

// fp16 scratch. g_qh is pre-scaled by 0.125*log2(e).
__device__ __half g_qh[NEL];
__device__ __half g_kh[NEL];
__device__ __half g_vh[NEL];
__device__ __half g_xh[GM*GK];
__device__ __half g_wth[3*GK*GK];   // W^T, [mat][n][k]

// ===========================================================================
// helpers
// ===========================================================================
__device__ __forceinline__ uint32_t smem_u32(const void* p) {
    uint32_t a;
    asm("{ .reg .u64 t; cvta.to.shared.u64 t, %1; cvt.u32.u64 %0, t; }" : "=r"(a) : "l"(p));
    return a;
}
__device__ __forceinline__ void ldsm4(uint32_t& r0, uint32_t& r1, uint32_t& r2, uint32_t& r3, uint32_t a) {
    asm volatile("ldmatrix.sync.aligned.m8n8.x4.shared.b16 {%0,%1,%2,%3}, [%4];"
                 : "=r"(r0), "=r"(r1), "=r"(r2), "=r"(r3) : "r"(a));
}
__device__ __forceinline__ void ldsm4t(uint32_t& r0, uint32_t& r1, uint32_t& r2, uint32_t& r3, uint32_t a) {
    asm volatile("ldmatrix.sync.aligned.m8n8.x4.trans.shared.b16 {%0,%1,%2,%3}, [%4];"
                 : "=r"(r0), "=r"(r1), "=r"(r2), "=r"(r3) : "r"(a));
}
__device__ __forceinline__ void mma_f16(float* c, uint32_t a0, uint32_t a1, uint32_t a2, uint32_t a3,
                                        uint32_t b0, uint32_t b1) {
    asm volatile("mma.sync.aligned.m16n8k16.row.col.f32.f16.f16.f32 "
                 "{%0,%1,%2,%3},{%4,%5,%6,%7},{%8,%9},{%0,%1,%2,%3};"
                 : "+f"(c[0]), "+f"(c[1]), "+f"(c[2]), "+f"(c[3])
                 : "r"(a0), "r"(a1), "r"(a2), "r"(a3), "r"(b0), "r"(b1));
}
__device__ __forceinline__ void cpa16(uint32_t s, const void* g) {
    asm volatile("cp.async.cg.shared.global [%0], [%1], 16;" :: "r"(s), "l"(g));
}
#define CPA_COMMIT() asm volatile("cp.async.commit_group;" ::: "memory")
#define CPA_WAIT(n)  asm volatile("cp.async.wait_group %0;" :: "n"(n) : "memory")

__device__ __forceinline__ uint32_t packh2(float a, float b) {
    __half2 h = __floats2half2_rn(a, b);
    return *reinterpret_cast<uint32_t*>(&h);
}
__device__ __forceinline__ uint32_t hadd2(uint32_t a, uint32_t b) {
    uint32_t d; asm("add.f16x2 %0, %1, %2;" : "=r"(d) : "r"(a), "r"(b)); return d;
}
__device__ __forceinline__ uint32_t ex2h2(uint32_t a) {
    uint32_t d; asm("ex2.approx.f16x2 %0, %1;" : "=r"(d) : "r"(a)); return d;
}

extern __shared__ char dyn_sm[];

// ===========================================================================
// Pre-pass 1: x -> fp16
// ===========================================================================
__global__ __launch_bounds__(256) void split_x_kernel(const float* __restrict__ x)
{
    int i = blockIdx.x * 256 + threadIdx.x;
    float4 v = ((const float4*)x)[i];
    uint2 hi = make_uint2(packh2(v.x, v.y), packh2(v.z, v.w));
    *(uint2*)&g_xh[(size_t)i * 4] = hi;
}

// ===========================================================================
// Pre-pass 2: transpose W -> W^T fp16
// ===========================================================================
__global__ __launch_bounds__(256) void split_w_kernel(
    const float* __restrict__ Wq, const float* __restrict__ Wk, const float* __restrict__ Wv)
{
    __shared__ float t[32][33];
    const int mat = blockIdx.z;
    const float* W = (mat == 0) ? Wq : (mat == 1) ? Wk : Wv;
    const int n0 = blockIdx.x * 32, k0 = blockIdx.y * 32;
    const int tx = threadIdx.x & 31, ty = threadIdx.x >> 5;

    #pragma unroll
    for (int i = 0; i < 4; i++)
        t[ty + i * 8][tx] = W[(size_t)(k0 + ty + i * 8) * GK + n0 + tx];
    __syncthreads();
    #pragma unroll
    for (int i = 0; i < 4; i++) {
        int n = n0 + ty + i * 8;
        int k = k0 + tx;
        g_wth[(size_t)mat * GK * GK + (size_t)n * GK + k] = __float2half_rn(t[tx][ty + i * 8]);
    }
}

// ===========================================================================
// QKV GEMM fp16. CTA 256x128 (8 warps of 64x64), K-tile 64, 3-stage cp.async,
// 1 CTA/SM. Halves W-side L2 traffic vs 128x128 (qkv was LTS-cap bound).
// ===========================================================================
#define XT 36864             // x tile: 256 rows x 144B
#define WT 18432             // W tile: 128 rows x 144B
#define QSTAGE (XT + WT)     // 55296
#define QSMEM  (3 * QSTAGE)  // 165888

__global__ __launch_bounds__(256, 1) void qkv_mma_kernel(
    const float* __restrict__ bq, const float* __restrict__ bk, const float* __restrict__ bv)
{
    const uint32_t sb = smem_u32(dyn_sm);
    const int tid = threadIdx.x;
    const int lane = tid & 31, warp = tid >> 5;
    const int warp_m = warp & 3, warp_n = warp >> 2;   // 4 m-warps x 2 n-warps

    const int mat = blockIdx.x >> 3;
    const int nmat0 = (blockIdx.x & 7) * 128;
    const int n0 = blockIdx.x * 128;
    const int m0 = blockIdx.y * 256;

    // prologue: issue stages 0 and 1
    #pragma unroll
    for (int st = 0; st < 2; st++) {
        #pragma unroll
        for (int l = 0; l < 12; l++) {
            int i = tid + l * 256;
            if (i < 2048) {
                int row = i >> 3, j = i & 7;
                cpa16(sb + st * QSTAGE + row * 144 + j * 16,
                      g_xh + (size_t)(m0 + row) * GK + st * 64 + j * 8);
            } else {
                int r = (i - 2048) >> 3, j = i & 7;
                cpa16(sb + st * QSTAGE + XT + r * 144 + j * 16,
                      g_wth + (size_t)(n0 + r) * GK + st * 64 + j * 8);
            }
        }
        CPA_COMMIT();
    }

    float acc[4][8][4];
    #pragma unroll
    for (int a = 0; a < 4; a++)
        #pragma unroll
        for (int c = 0; c < 8; c++)
            #pragma unroll
            for (int d = 0; d < 4; d++) acc[a][c][d] = 0.f;

    const int mbase = warp_m * 64 + (lane & 7) + ((lane & 8) ? 8 : 0);
    const int nbase = warp_n * 64 + (lane & 7) + ((lane & 16) ? 8 : 0);

    int buf = 0;
    for (int kt = 0; kt < GK / 64; kt++) {
        if (kt < GK / 64 - 1) { CPA_WAIT(1); } else { CPA_WAIT(0); }
        __syncthreads();

        if (kt + 2 < GK / 64) {
            int ib = (kt + 2) % 3;
            int k0 = (kt + 2) * 64;
            #pragma unroll
            for (int l = 0; l < 12; l++) {
                int i = tid + l * 256;
                if (i < 2048) {
                    int row = i >> 3, j = i & 7;
                    cpa16(sb + ib * QSTAGE + row * 144 + j * 16,
                          g_xh + (size_t)(m0 + row) * GK + k0 + j * 8);
                } else {
                    int r = (i - 2048) >> 3, j = i & 7;
                    cpa16(sb + ib * QSTAGE + XT + r * 144 + j * 16,
                          g_wth + (size_t)(n0 + r) * GK + k0 + j * 8);
                }
            }
            CPA_COMMIT();
        }

        const uint32_t ab = sb + buf * QSTAGE;
        buf = (buf + 1) % 3;

        #define QB_ADDR(kk_, nf_) (ab + XT + (uint32_t)(nbase + (nf_) * 16) * 144 \
                                   + (uint32_t)((kk_) * 16 + ((lane & 8) ? 8 : 0)) * 2)

        uint32_t bcur0, bcur1, bcur2, bcur3;
        ldsm4(bcur0, bcur1, bcur2, bcur3, QB_ADDR(0, 0));

        #pragma unroll
        for (int kk = 0; kk < 4; kk++) {
            const uint32_t acol = (uint32_t)(kk * 16 + ((lane & 16) ? 8 : 0)) * 2;
            uint32_t ah[4][4];
            #pragma unroll
            for (int mf = 0; mf < 4; mf++) {
                uint32_t addr = ab + (uint32_t)(mbase + mf * 16) * 144 + acol;
                ldsm4(ah[mf][0], ah[mf][1], ah[mf][2], ah[mf][3], addr);
            }
            #pragma unroll
            for (int nf = 0; nf < 4; nf++) {
                uint32_t bn0, bn1, bn2, bn3;
                int flat = kk * 4 + nf;
                if (flat < 15) {
                    int nk = (flat + 1) >> 2, nn = (flat + 1) & 3;
                    ldsm4(bn0, bn1, bn2, bn3, QB_ADDR(nk, nn));
                }
                #pragma unroll
                for (int mf = 0; mf < 4; mf++) {
                    mma_f16(acc[mf][2*nf],   ah[mf][0], ah[mf][1], ah[mf][2], ah[mf][3], bcur0, bcur1);
                    mma_f16(acc[mf][2*nf+1], ah[mf][0], ah[mf][1], ah[mf][2], ah[mf][3], bcur2, bcur3);
                }
                if (flat < 15) { bcur0 = bn0; bcur1 = bn1; bcur2 = bn2; bcur3 = bn3; }
            }
        }
        #undef QB_ADDR
    }

    // epilogue (Q output pre-scaled by 0.125*log2e for the attention kernel)
    const float* biasp = (mat == 0) ? bq : (mat == 1) ? bk : bv;
    __half* ohp = (mat == 0) ? g_qh : (mat == 1) ? g_kh : g_vh;
    const float qscale = (mat == 0) ? 0.125f * 1.44269504f : 1.0f;

    #pragma unroll
    for (int mf = 0; mf < 4; mf++) {
        #pragma unroll
        for (int hf = 0; hf < 2; hf++) {
            int gm = m0 + warp_m * 64 + mf * 16 + (lane >> 2) + hf * 8;
            int bb = gm >> 11, s = gm & 2047;
            #pragma unroll
            for (int nf = 0; nf < 8; nf++) {
                int cn = nmat0 + warp_n * 64 + nf * 8 + 2 * (lane & 3);
                float2 bv2 = *(const float2*)&biasp[cn];
                float v0 = (acc[mf][nf][hf * 2 + 0] + bv2.x) * qscale;
                float v1 = (acc[mf][nf][hf * 2 + 1] + bv2.y) * qscale;
                int hh = cn >> 6, w = cn & 63;
                size_t idx = (((size_t)bb * HH + hh) * SS + s) * WW + w;
                *(uint32_t*)&ohp[idx] = packh2(v0, v1);
            }
        }
    }
}

// ===========================================================================
// fp16 flash attention: log2-domain scores, f16x2 softmax, explicit SW
// pipelining. NEW: wave-slot-B CTAs spin ~600 cyc at start to phase-offset
// the co-resident CTA pair (softmax of one overlaps MMAs of the other);
// mask-bias words prefetched into regs before the S-GEMM.
// CTA 128 thr = 4 warps x 32 q-rows, K-tile 64, 3-stage cp.async, 2 CTAs/SM.
// ===========================================================================
#define ASTG 9216                       // one 64x144B tile
#define SO_QQ   (6 * ASTG)              // 55296 (3 stages x {K,V})
#define SO_BIAS (SO_QQ + 18432)         // 73728
#define ASMEM   (SO_BIAS + (SS/2) * 4)  // 77824

__global__ __launch_bounds__(128, 2) void attn_f16_kernel(
    const int* __restrict__ mask, float* __restrict__ out)
{
    const uint32_t sb = smem_u32(dyn_sm);
    uint32_t* biash = (uint32_t*)(dyn_sm + SO_BIAS);   // half2 per key pair
    const int tid = threadIdx.x;
    const int lane = tid & 31, warp = tid >> 5;
    const int bh = blockIdx.y;
    const int b = bh / HH, h = bh % HH;
    const int q0 = blockIdx.x * 128;
    const size_t bhoff = (size_t)bh * SS * WW;

    // Phase-stagger wave-slot-B CTAs so co-resident pairs are desynchronized:
    // the sibling warp on each SMSP then has MMAs to issue during this CTA's
    // softmax windows. Timing-only; results unchanged.
    {
        int linear = blockIdx.x + gridDim.x * blockIdx.y;
        if ((linear / 148) & 1) {
            long long t0 = clock64();
            while (clock64() - t0 < 600) { }
        }
    }

    // mask -> half2 additive bias (0 or -30000; ex2 underflows to 0)
    for (int i = tid; i < SS / 2; i += 128) {
        int mv0 = mask[b * SS + 2 * i];
        int mv1 = mask[b * SS + 2 * i + 1];
        biash[i] = packh2(mv0 ? 0.f : -30000.f, mv1 ? 0.f : -30000.f);
    }

    // stage Q (128 rows)
    #pragma unroll
    for (int l = 0; l < 8; l++) {
        int i = tid + l * 128;
        int r = i >> 3, j = i & 7;
        cpa16(sb + SO_QQ + r * 144 + j * 16, g_qh + bhoff + (size_t)(q0 + r) * WW + j * 8);
    }
    CPA_COMMIT();

    // stages 0 and 1 of K/V
    #pragma unroll
    for (int st = 0; st < 2; st++) {
        #pragma unroll
        for (int l = 0; l < 8; l++) {
            int i = tid + l * 128;
            int sel = i >> 9, rem = i & 511;
            int r = rem >> 3, j = rem & 7;
            const __half* src = (sel ? g_vh : g_kh) + bhoff + (size_t)(st * 64 + r) * WW + j * 8;
            cpa16(sb + st * 2 * ASTG + sel * ASTG + r * 144 + j * 16, src);
        }
        CPA_COMMIT();
    }

    CPA_WAIT(2);    // Q done
    __syncthreads();

    // Q fragments: 2 m16 frags x 4 k16 frags, register-resident
    uint32_t qh[2][4][4];
    #pragma unroll
    for (int mf = 0; mf < 2; mf++) {
        int row = warp * 32 + mf * 16 + (lane & 7) + ((lane & 8) ? 8 : 0);
        #pragma unroll
        for (int ks = 0; ks < 4; ks++) {
            int col = ks * 16 + ((lane & 16) ? 8 : 0);
            uint32_t a = sb + SO_QQ + row * 144 + col * 2;
            ldsm4(qh[mf][ks][0], qh[mf][ks][1], qh[mf][ks][2], qh[mf][ks][3], a);
        }
    }

    float lacc[2][2] = {{0.f, 0.f}, {0.f, 0.f}};
    float o[2][8][4];
    #pragma unroll
    for (int mf = 0; mf < 2; mf++)
        #pragma unroll
        for (int i = 0; i < 8; i++)
            #pragma unroll
            for (int j = 0; j < 4; j++) o[mf][i][j] = 0.f;

    int buf = 0;
    for (int kt = 0; kt < SS / 64; kt++) {
        if (kt < SS / 64 - 1) { CPA_WAIT(1); } else { CPA_WAIT(0); }
        __syncthreads();

        if (kt + 2 < SS / 64) {
            int ib = (kt + 2) % 3;
            size_t srow = (size_t)(kt + 2) * 64;
            #pragma unroll
            for (int l = 0; l < 8; l++) {
                int i = tid + l * 128;
                int sel = i >> 9, rem = i & 511;
                int r = rem >> 3, j = rem & 7;
                const __half* src = (sel ? g_vh : g_kh) + bhoff + (srow + r) * WW + j * 8;
                cpa16(sb + ib * 2 * ASTG + sel * ASTG + r * 144 + j * 16, src);
            }
            CPA_COMMIT();
        }

        const uint32_t kb = sb + buf * 2 * ASTG;
        buf = (buf + 1) % 3;

        // Prefetch this tile's bias words into regs (off the exp chain)
        uint32_t bih[8];
        #pragma unroll
        for (int nt = 0; nt < 8; nt++)
            bih[nt] = biash[(kt * 64 + nt * 8 + 2 * (lane & 3)) >> 1];

        #define K_ADDR(ks_, np_) (kb + (uint32_t)((np_) * 16 + (lane & 7) + ((lane & 16) ? 8 : 0)) * 144 \
                                  + (uint32_t)((ks_) * 16 + ((lane & 8) ? 8 : 0)) * 2)
        #define V_ADDR(ks_, vp_) (kb + ASTG + (uint32_t)((ks_) * 16 + (lane & 7) + ((lane & 8) ? 8 : 0)) * 144 \
                                  + (uint32_t)((vp_) * 16 + ((lane & 16) ? 8 : 0)) * 2)

        // ---- S = Q * K^T, K-frag prefetch 1 LDSM ahead ----
        float s[2][8][4];
        #pragma unroll
        for (int mf = 0; mf < 2; mf++)
            #pragma unroll
            for (int i = 0; i < 8; i++)
                #pragma unroll
                for (int j = 0; j < 4; j++) s[mf][i][j] = 0.f;

        {
            uint32_t kc0, kc1, kc2, kc3;
            ldsm4(kc0, kc1, kc2, kc3, K_ADDR(0, 0));
            #pragma unroll
            for (int it = 0; it < 16; it++) {
                int ks = it >> 2, np = it & 3;
                uint32_t kn0, kn1, kn2, kn3;
                if (it < 15) {
                    int nk = (it + 1) >> 2, nn = (it + 1) & 3;
                    ldsm4(kn0, kn1, kn2, kn3, K_ADDR(nk, nn));
                }
                #pragma unroll
                for (int mf = 0; mf < 2; mf++) {
                    mma_f16(s[mf][2 * np],     qh[mf][ks][0], qh[mf][ks][1], qh[mf][ks][2], qh[mf][ks][3], kc0, kc1);
                    mma_f16(s[mf][2 * np + 1], qh[mf][ks][0], qh[mf][ks][1], qh[mf][ks][2], qh[mf][ks][3], kc2, kc3);
                }
                if (it < 15) { kc0 = kn0; kc1 = kn1; kc2 = kn2; kc3 = kn3; }
            }
        }

        // ---- softmax + PV: p double-buffered one block ahead, V prefetch ----
        uint32_t lh[2][2] = {{0u, 0u}, {0u, 0u}};
        uint32_t pb[2][2][4];    // [buf][mf][4]

        #pragma unroll
        for (int t = 0; t < 2; t++) {
            #pragma unroll
            for (int mf = 0; mf < 2; mf++) {
                uint32_t a0 = ex2h2(hadd2(packh2(s[mf][t][0], s[mf][t][1]), bih[t]));
                uint32_t a1 = ex2h2(hadd2(packh2(s[mf][t][2], s[mf][t][3]), bih[t]));
                pb[0][mf][2 * t]     = a0;
                pb[0][mf][2 * t + 1] = a1;
                lh[mf][0] = hadd2(lh[mf][0], a0);
                lh[mf][1] = hadd2(lh[mf][1], a1);
            }
        }

        uint32_t vc0, vc1, vc2, vc3;
        ldsm4t(vc0, vc1, vc2, vc3, V_ADDR(0, 0));

        #pragma unroll
        for (int ks = 0; ks < 4; ks++) {
            int cb = ks & 1;
            if (ks < 3) {
                #pragma unroll
                for (int t = 0; t < 2; t++) {
                    int nt = 2 * (ks + 1) + t;
                    #pragma unroll
                    for (int mf = 0; mf < 2; mf++) {
                        uint32_t a0 = ex2h2(hadd2(packh2(s[mf][nt][0], s[mf][nt][1]), bih[nt]));
                        uint32_t a1 = ex2h2(hadd2(packh2(s[mf][nt][2], s[mf][nt][3]), bih[nt]));
                        pb[cb ^ 1][mf][2 * t]     = a0;
                        pb[cb ^ 1][mf][2 * t + 1] = a1;
                        lh[mf][0] = hadd2(lh[mf][0], a0);
                        lh[mf][1] = hadd2(lh[mf][1], a1);
                    }
                }
            }
            #pragma unroll
            for (int vp = 0; vp < 4; vp++) {
                uint32_t vn0, vn1, vn2, vn3;
                int flat = ks * 4 + vp;
                if (flat < 15) {
                    int nk = (flat + 1) >> 2, nv = (flat + 1) & 3;
                    ldsm4t(vn0, vn1, vn2, vn3, V_ADDR(nk, nv));
                }
                #pragma unroll
                for (int mf = 0; mf < 2; mf++) {
                    mma_f16(o[mf][2 * vp],     pb[cb][mf][0], pb[cb][mf][1], pb[cb][mf][2], pb[cb][mf][3], vc0, vc1);
                    mma_f16(o[mf][2 * vp + 1], pb[cb][mf][0], pb[cb][mf][1], pb[cb][mf][2], pb[cb][mf][3], vc2, vc3);
                }
                if (flat < 15) { vc0 = vn0; vc1 = vn1; vc2 = vn2; vc3 = vn3; }
            }
        }
        #undef K_ADDR
        #undef V_ADDR

        #pragma unroll
        for (int mf = 0; mf < 2; mf++) {
            float2 f0 = __half22float2(*(__half2*)&lh[mf][0]);
            float2 f1 = __half22float2(*(__half2*)&lh[mf][1]);
            lacc[mf][0] += f0.x + f0.y;
            lacc[mf][1] += f1.x + f1.y;
        }
    }

    // ---- final l reduction + epilogue ----
    #pragma unroll
    for (int mf = 0; mf < 2; mf++)
        #pragma unroll
        for (int i = 0; i < 2; i++) {
            lacc[mf][i] += __shfl_xor_sync(0xffffffffu, lacc[mf][i], 1);
            lacc[mf][i] += __shfl_xor_sync(0xffffffffu, lacc[mf][i], 2);
        }
    #pragma unroll
    for (int mf = 0; mf < 2; mf++) {
        float inv0 = 1.0f / lacc[mf][0];
        float inv1 = 1.0f / lacc[mf][1];
        int r0 = q0 + warp * 32 + mf * 16 + (lane >> 2);
        int r1 = r0 + 8;
        size_t base0 = ((size_t)b * SS + r0) * DD + h * WW + 2 * (lane & 3);
        size_t base1 = ((size_t)b * SS + r1) * DD + h * WW + 2 * (lane & 3);
        #pragma unroll
        for (int nt = 0; nt < 8; nt++) {
            *(float2*)&out[base0 + nt * 8] = make_float2(o[mf][nt][0] * inv0, o[mf][nt][1] * inv0);
            *(float2*)&out[base1 + nt * 8] = make_float2(o[mf][nt][2] * inv1, o[mf][nt][3] * inv1);
        }
    }
}

// ===========================================================================
// Launch
// ===========================================================================
extern "C" void kernel_launch(void* const* d_in, const int* in_sizes, int n_in,
                              void* d_out, int out_size)
{
    const float* x  = (const float*)d_in[0];
    const int* mask = (const int*)d_in[1];
    const float* Wq = (const float*)d_in[2];
    const float* bq = (const float*)d_in[3];
    const float* Wk = (const float*)d_in[4];
    const float* bk = (const float*)d_in[5];
    const float* Wv = (const float*)d_in[6];
    const float* bv = (const float*)d_in[7];
    float* out = (float*)d_out;

    cudaFuncSetAttribute(qkv_mma_kernel, cudaFuncAttributeMaxDynamicSharedMemorySize, QSMEM);
    cudaFuncSetAttribute(attn_f16_kernel, cudaFuncAttributeMaxDynamicSharedMemorySize, ASMEM);

    split_x_kernel<<<GM * GK / 1024, 256>>>(x);
    dim3 gw(GK / 32, GK / 32, 3);
    split_w_kernel<<<gw, 256>>>(Wq, Wk, Wv);

    dim3 g1(GN / 128, GM / 256);   // (24, 32)
    qkv_mma_kernel<<<g1, 256, QSMEM>>>(bq, bk, bv);

    dim3 g2(SS / 128, BB * HH);    // (16, 64)
    attn_f16_kernel<<<g2, 128, ASMEM>>>(mask, out);
}

// round 12
// speedup vs baseline: 1.0844x; 1.0844x over previous
#include <cuda_runtime.h>
#include <cuda_fp16.h>
#include <cstdint>

// Problem dims
#define BB 4
#define SS 2048
#define DD 1024
#define HH 16
#define WW 64
#define NEL (BB*HH*SS*WW)
#define GM 8192
#define GK 1024
#define GN 3072

// fp16 scratch. g_qh is pre-scaled by 0.125*log2(e).
__device__ __half g_qh[NEL];
__device__ __half g_kh[NEL];
__device__ __half g_vh[NEL];
__device__ __half g_xh[GM*GK];
__device__ __half g_w16[3*GK*GK];   // W in native [mat][k][n] layout, fp16

// ===========================================================================
// helpers
// ===========================================================================
__device__ __forceinline__ uint32_t smem_u32(const void* p) {
    uint32_t a;
    asm("{ .reg .u64 t; cvta.to.shared.u64 t, %1; cvt.u32.u64 %0, t; }" : "=r"(a) : "l"(p));
    return a;
}
__device__ __forceinline__ void ldsm4(uint32_t& r0, uint32_t& r1, uint32_t& r2, uint32_t& r3, uint32_t a) {
    asm volatile("ldmatrix.sync.aligned.m8n8.x4.shared.b16 {%0,%1,%2,%3}, [%4];"
                 : "=r"(r0), "=r"(r1), "=r"(r2), "=r"(r3) : "r"(a));
}
__device__ __forceinline__ void ldsm4t(uint32_t& r0, uint32_t& r1, uint32_t& r2, uint32_t& r3, uint32_t a) {
    asm volatile("ldmatrix.sync.aligned.m8n8.x4.trans.shared.b16 {%0,%1,%2,%3}, [%4];"
                 : "=r"(r0), "=r"(r1), "=r"(r2), "=r"(r3) : "r"(a));
}
__device__ __forceinline__ void mma_f16(float* c, uint32_t a0, uint32_t a1, uint32_t a2, uint32_t a3,
                                        uint32_t b0, uint32_t b1) {
    asm volatile("mma.sync.aligned.m16n8k16.row.col.f32.f16.f16.f32 "
                 "{%0,%1,%2,%3},{%4,%5,%6,%7},{%8,%9},{%0,%1,%2,%3};"
                 : "+f"(c[0]), "+f"(c[1]), "+f"(c[2]), "+f"(c[3])
                 : "r"(a0), "r"(a1), "r"(a2), "r"(a3), "r"(b0), "r"(b1));
}
__device__ __forceinline__ void cpa16(uint32_t s, const void* g) {
    asm volatile("cp.async.cg.shared.global [%0], [%1], 16;" :: "r"(s), "l"(g));
}
#define CPA_COMMIT() asm volatile("cp.async.commit_group;" ::: "memory")
#define CPA_WAIT(n)  asm volatile("cp.async.wait_group %0;" :: "n"(n) : "memory")

__device__ __forceinline__ uint32_t packh2(float a, float b) {
    __half2 h = __floats2half2_rn(a, b);
    return *reinterpret_cast<uint32_t*>(&h);
}
__device__ __forceinline__ uint32_t hadd2(uint32_t a, uint32_t b) {
    uint32_t d; asm("add.f16x2 %0, %1, %2;" : "=r"(d) : "r"(a), "r"(b)); return d;
}
__device__ __forceinline__ uint32_t ex2h2(uint32_t a) {
    uint32_t d; asm("ex2.approx.f16x2 %0, %1;" : "=r"(d) : "r"(a)); return d;
}

extern __shared__ char dyn_sm[];

// ===========================================================================
// Pre-pass 1: x -> fp16
// ===========================================================================
__global__ __launch_bounds__(256) void split_x_kernel(const float* __restrict__ x)
{
    int i = blockIdx.x * 256 + threadIdx.x;
    float4 v = ((const float4*)x)[i];
    uint2 hi = make_uint2(packh2(v.x, v.y), packh2(v.z, v.w));
    *(uint2*)&g_xh[(size_t)i * 4] = hi;
}

// ===========================================================================
// Pre-pass 2: W -> fp16, NATIVE layout (no transpose; B uses ldsm4t)
// ===========================================================================
__global__ __launch_bounds__(256) void conv_w_kernel(
    const float* __restrict__ Wq, const float* __restrict__ Wk, const float* __restrict__ Wv)
{
    const int mat = blockIdx.y;
    const float* W = (mat == 0) ? Wq : (mat == 1) ? Wk : Wv;
    int i = blockIdx.x * 256 + threadIdx.x;          // float4 index within matrix
    float4 v = ((const float4*)W)[i];
    uint2 hv = make_uint2(packh2(v.x, v.y), packh2(v.z, v.w));
    *(uint2*)&g_w16[(size_t)mat * GK * GK + (size_t)i * 4] = hv;
}

// ===========================================================================
// QKV GEMM fp16 (R8 shape: CTA 128x128, 4 warps of 64x64, K-tile 64,
// 3-stage cp.async, 2 CTAs/SM). B operand read from NATIVE [k][n] W tiles
// via ldsm4t (same pattern as the attention kernel's V path).
// x tile: 128 rows x 144B. W tile: 64 k-rows x 272B (128 n fp16 + pad).
// ===========================================================================
#define XT 18432             // 128 * 144
#define WT 17408             // 64 * 272
#define QSTAGE (XT + WT)     // 35840
#define QSMEM  (3 * QSTAGE)  // 107520

__global__ __launch_bounds__(128, 2) void qkv_mma_kernel(
    const float* __restrict__ bq, const float* __restrict__ bk, const float* __restrict__ bv)
{
    const uint32_t sb = smem_u32(dyn_sm);
    const int tid = threadIdx.x;
    const int lane = tid & 31, warp = tid >> 5;
    const int warp_m = warp & 1, warp_n = warp >> 1;

    const int mat = blockIdx.x >> 3;
    const int nmat0 = (blockIdx.x & 7) * 128;
    const int m0 = blockIdx.y * 128;

    const __half* xsrc = g_xh + (size_t)m0 * GK;
    const __half* wsrc = g_w16 + (size_t)mat * GK * GK + nmat0;

    // prologue: stages 0 and 1 (2048 chunks each, 128 thr -> 16 iters)
    #pragma unroll
    for (int st = 0; st < 2; st++) {
        #pragma unroll
        for (int l = 0; l < 16; l++) {
            int i = tid + l * 128;
            if (i < 1024) {
                int row = i >> 3, j = i & 7;
                cpa16(sb + st * QSTAGE + row * 144 + j * 16,
                      xsrc + (size_t)row * GK + st * 64 + j * 8);
            } else {
                int idx = i - 1024;
                int kr = idx >> 4, j = idx & 15;
                cpa16(sb + st * QSTAGE + XT + kr * 272 + j * 16,
                      wsrc + (size_t)(st * 64 + kr) * GK + j * 8);
            }
        }
        CPA_COMMIT();
    }

    float acc[4][8][4];
    #pragma unroll
    for (int a = 0; a < 4; a++)
        #pragma unroll
        for (int c = 0; c < 8; c++)
            #pragma unroll
            for (int d = 0; d < 4; d++) acc[a][c][d] = 0.f;

    const int mbase = warp_m * 64 + (lane & 7) + ((lane & 8) ? 8 : 0);

    int buf = 0;
    for (int kt = 0; kt < GK / 64; kt++) {
        if (kt < GK / 64 - 1) { CPA_WAIT(1); } else { CPA_WAIT(0); }
        __syncthreads();

        if (kt + 2 < GK / 64) {
            int ib = (kt + 2) % 3;
            int k0 = (kt + 2) * 64;
            #pragma unroll
            for (int l = 0; l < 16; l++) {
                int i = tid + l * 128;
                if (i < 1024) {
                    int row = i >> 3, j = i & 7;
                    cpa16(sb + ib * QSTAGE + row * 144 + j * 16,
                          xsrc + (size_t)row * GK + k0 + j * 8);
                } else {
                    int idx = i - 1024;
                    int kr = idx >> 4, j = idx & 15;
                    cpa16(sb + ib * QSTAGE + XT + kr * 272 + j * 16,
                          wsrc + (size_t)(k0 + kr) * GK + j * 8);
                }
            }
            CPA_COMMIT();
        }

        const uint32_t ab = sb + buf * QSTAGE;
        buf = (buf + 1) % 3;

        // B-fragment: trans-ldmatrix from native [k][n] tile (mirrors attn V)
        #define QB_ADDR(kk_, nf_) (ab + XT \
            + (uint32_t)((kk_) * 16 + (lane & 7) + ((lane & 8) ? 8 : 0)) * 272 \
            + (uint32_t)(warp_n * 64 + (nf_) * 16 + ((lane & 16) ? 8 : 0)) * 2)

        uint32_t bcur0, bcur1, bcur2, bcur3;
        ldsm4t(bcur0, bcur1, bcur2, bcur3, QB_ADDR(0, 0));

        #pragma unroll
        for (int kk = 0; kk < 4; kk++) {
            const uint32_t acol = (uint32_t)(kk * 16 + ((lane & 16) ? 8 : 0)) * 2;
            uint32_t ah[4][4];
            #pragma unroll
            for (int mf = 0; mf < 4; mf++) {
                uint32_t addr = ab + (uint32_t)(mbase + mf * 16) * 144 + acol;
                ldsm4(ah[mf][0], ah[mf][1], ah[mf][2], ah[mf][3], addr);
            }
            #pragma unroll
            for (int nf = 0; nf < 4; nf++) {
                uint32_t bn0, bn1, bn2, bn3;
                int flat = kk * 4 + nf;
                if (flat < 15) {
                    int nk = (flat + 1) >> 2, nn = (flat + 1) & 3;
                    ldsm4t(bn0, bn1, bn2, bn3, QB_ADDR(nk, nn));
                }
                #pragma unroll
                for (int mf = 0; mf < 4; mf++) {
                    mma_f16(acc[mf][2*nf],   ah[mf][0], ah[mf][1], ah[mf][2], ah[mf][3], bcur0, bcur1);
                    mma_f16(acc[mf][2*nf+1], ah[mf][0], ah[mf][1], ah[mf][2], ah[mf][3], bcur2, bcur3);
                }
                if (flat < 15) { bcur0 = bn0; bcur1 = bn1; bcur2 = bn2; bcur3 = bn3; }
            }
        }
        #undef QB_ADDR
    }

    // epilogue (Q output pre-scaled by 0.125*log2e for the attention kernel)
    const float* biasp = (mat == 0) ? bq : (mat == 1) ? bk : bv;
    __half* ohp = (mat == 0) ? g_qh : (mat == 1) ? g_kh : g_vh;
    const float qscale = (mat == 0) ? 0.125f * 1.44269504f : 1.0f;

    #pragma unroll
    for (int mf = 0; mf < 4; mf++) {
        #pragma unroll
        for (int hf = 0; hf < 2; hf++) {
            int gm = m0 + warp_m * 64 + mf * 16 + (lane >> 2) + hf * 8;
            int bb = gm >> 11, s = gm & 2047;
            #pragma unroll
            for (int nf = 0; nf < 8; nf++) {
                int cn = nmat0 + warp_n * 64 + nf * 8 + 2 * (lane & 3);
                float2 bv2 = *(const float2*)&biasp[cn];
                float v0 = (acc[mf][nf][hf * 2 + 0] + bv2.x) * qscale;
                float v1 = (acc[mf][nf][hf * 2 + 1] + bv2.y) * qscale;
                int hh = cn >> 6, w = cn & 63;
                size_t idx = (((size_t)bb * HH + hh) * SS + s) * WW + w;
                *(uint32_t*)&ohp[idx] = packh2(v0, v1);
            }
        }
    }
}

// ===========================================================================
// fp16 flash attention (R11 version: stagger + bias reg-prefetch kept).
// ===========================================================================
#define ASTG 9216                       // one 64x144B tile
#define SO_QQ   (6 * ASTG)              // 55296 (3 stages x {K,V})
#define SO_BIAS (SO_QQ + 18432)         // 73728
#define ASMEM   (SO_BIAS + (SS/2) * 4)  // 77824

__global__ __launch_bounds__(128, 2) void attn_f16_kernel(
    const int* __restrict__ mask, float* __restrict__ out)
{
    const uint32_t sb = smem_u32(dyn_sm);
    uint32_t* biash = (uint32_t*)(dyn_sm + SO_BIAS);
    const int tid = threadIdx.x;
    const int lane = tid & 31, warp = tid >> 5;
    const int bh = blockIdx.y;
    const int b = bh / HH, h = bh % HH;
    const int q0 = blockIdx.x * 128;
    const size_t bhoff = (size_t)bh * SS * WW;

    // Phase-stagger wave-slot-B CTAs (timing only; results unchanged).
    {
        int linear = blockIdx.x + gridDim.x * blockIdx.y;
        if ((linear / 148) & 1) {
            long long t0 = clock64();
            while (clock64() - t0 < 600) { }
        }
    }

    for (int i = tid; i < SS / 2; i += 128) {
        int mv0 = mask[b * SS + 2 * i];
        int mv1 = mask[b * SS + 2 * i + 1];
        biash[i] = packh2(mv0 ? 0.f : -30000.f, mv1 ? 0.f : -30000.f);
    }

    #pragma unroll
    for (int l = 0; l < 8; l++) {
        int i = tid + l * 128;
        int r = i >> 3, j = i & 7;
        cpa16(sb + SO_QQ + r * 144 + j * 16, g_qh + bhoff + (size_t)(q0 + r) * WW + j * 8);
    }
    CPA_COMMIT();

    #pragma unroll
    for (int st = 0; st < 2; st++) {
        #pragma unroll
        for (int l = 0; l < 8; l++) {
            int i = tid + l * 128;
            int sel = i >> 9, rem = i & 511;
            int r = rem >> 3, j = rem & 7;
            const __half* src = (sel ? g_vh : g_kh) + bhoff + (size_t)(st * 64 + r) * WW + j * 8;
            cpa16(sb + st * 2 * ASTG + sel * ASTG + r * 144 + j * 16, src);
        }
        CPA_COMMIT();
    }

    CPA_WAIT(2);
    __syncthreads();

    uint32_t qh[2][4][4];
    #pragma unroll
    for (int mf = 0; mf < 2; mf++) {
        int row = warp * 32 + mf * 16 + (lane & 7) + ((lane & 8) ? 8 : 0);
        #pragma unroll
        for (int ks = 0; ks < 4; ks++) {
            int col = ks * 16 + ((lane & 16) ? 8 : 0);
            uint32_t a = sb + SO_QQ + row * 144 + col * 2;
            ldsm4(qh[mf][ks][0], qh[mf][ks][1], qh[mf][ks][2], qh[mf][ks][3], a);
        }
    }

    float lacc[2][2] = {{0.f, 0.f}, {0.f, 0.f}};
    float o[2][8][4];
    #pragma unroll
    for (int mf = 0; mf < 2; mf++)
        #pragma unroll
        for (int i = 0; i < 8; i++)
            #pragma unroll
            for (int j = 0; j < 4; j++) o[mf][i][j] = 0.f;

    int buf = 0;
    for (int kt = 0; kt < SS / 64; kt++) {
        if (kt < SS / 64 - 1) { CPA_WAIT(1); } else { CPA_WAIT(0); }
        __syncthreads();

        if (kt + 2 < SS / 64) {
            int ib = (kt + 2) % 3;
            size_t srow = (size_t)(kt + 2) * 64;
            #pragma unroll
            for (int l = 0; l < 8; l++) {
                int i = tid + l * 128;
                int sel = i >> 9, rem = i & 511;
                int r = rem >> 3, j = rem & 7;
                const __half* src = (sel ? g_vh : g_kh) + bhoff + (srow + r) * WW + j * 8;
                cpa16(sb + ib * 2 * ASTG + sel * ASTG + r * 144 + j * 16, src);
            }
            CPA_COMMIT();
        }

        const uint32_t kb = sb + buf * 2 * ASTG;
        buf = (buf + 1) % 3;

        uint32_t bih[8];
        #pragma unroll
        for (int nt = 0; nt < 8; nt++)
            bih[nt] = biash[(kt * 64 + nt * 8 + 2 * (lane & 3)) >> 1];

        #define K_ADDR(ks_, np_) (kb + (uint32_t)((np_) * 16 + (lane & 7) + ((lane & 16) ? 8 : 0)) * 144 \
                                  + (uint32_t)((ks_) * 16 + ((lane & 8) ? 8 : 0)) * 2)
        #define V_ADDR(ks_, vp_) (kb + ASTG + (uint32_t)((ks_) * 16 + (lane & 7) + ((lane & 8) ? 8 : 0)) * 144 \
                                  + (uint32_t)((vp_) * 16 + ((lane & 16) ? 8 : 0)) * 2)

        float s[2][8][4];
        #pragma unroll
        for (int mf = 0; mf < 2; mf++)
            #pragma unroll
            for (int i = 0; i < 8; i++)
                #pragma unroll
                for (int j = 0; j < 4; j++) s[mf][i][j] = 0.f;

        {
            uint32_t kc0, kc1, kc2, kc3;
            ldsm4(kc0, kc1, kc2, kc3, K_ADDR(0, 0));
            #pragma unroll
            for (int it = 0; it < 16; it++) {
                int ks = it >> 2, np = it & 3;
                uint32_t kn0, kn1, kn2, kn3;
                if (it < 15) {
                    int nk = (it + 1) >> 2, nn = (it + 1) & 3;
                    ldsm4(kn0, kn1, kn2, kn3, K_ADDR(nk, nn));
                }
                #pragma unroll
                for (int mf = 0; mf < 2; mf++) {
                    mma_f16(s[mf][2 * np],     qh[mf][ks][0], qh[mf][ks][1], qh[mf][ks][2], qh[mf][ks][3], kc0, kc1);
                    mma_f16(s[mf][2 * np + 1], qh[mf][ks][0], qh[mf][ks][1], qh[mf][ks][2], qh[mf][ks][3], kc2, kc3);
                }
                if (it < 15) { kc0 = kn0; kc1 = kn1; kc2 = kn2; kc3 = kn3; }
            }
        }

        uint32_t lh[2][2] = {{0u, 0u}, {0u, 0u}};
        uint32_t pb[2][2][4];

        #pragma unroll
        for (int t = 0; t < 2; t++) {
            #pragma unroll
            for (int mf = 0; mf < 2; mf++) {
                uint32_t a0 = ex2h2(hadd2(packh2(s[mf][t][0], s[mf][t][1]), bih[t]));
                uint32_t a1 = ex2h2(hadd2(packh2(s[mf][t][2], s[mf][t][3]), bih[t]));
                pb[0][mf][2 * t]     = a0;
                pb[0][mf][2 * t + 1] = a1;
                lh[mf][0] = hadd2(lh[mf][0], a0);
                lh[mf][1] = hadd2(lh[mf][1], a1);
            }
        }

        uint32_t vc0, vc1, vc2, vc3;
        ldsm4t(vc0, vc1, vc2, vc3, V_ADDR(0, 0));

        #pragma unroll
        for (int ks = 0; ks < 4; ks++) {
            int cb = ks & 1;
            if (ks < 3) {
                #pragma unroll
                for (int t = 0; t < 2; t++) {
                    int nt = 2 * (ks + 1) + t;
                    #pragma unroll
                    for (int mf = 0; mf < 2; mf++) {
                        uint32_t a0 = ex2h2(hadd2(packh2(s[mf][nt][0], s[mf][nt][1]), bih[nt]));
                        uint32_t a1 = ex2h2(hadd2(packh2(s[mf][nt][2], s[mf][nt][3]), bih[nt]));
                        pb[cb ^ 1][mf][2 * t]     = a0;
                        pb[cb ^ 1][mf][2 * t + 1] = a1;
                        lh[mf][0] = hadd2(lh[mf][0], a0);
                        lh[mf][1] = hadd2(lh[mf][1], a1);
                    }
                }
            }
            #pragma unroll
            for (int vp = 0; vp < 4; vp++) {
                uint32_t vn0, vn1, vn2, vn3;
                int flat = ks * 4 + vp;
                if (flat < 15) {
                    int nk = (flat + 1) >> 2, nv = (flat + 1) & 3;
                    ldsm4t(vn0, vn1, vn2, vn3, V_ADDR(nk, nv));
                }
                #pragma unroll
                for (int mf = 0; mf < 2; mf++) {
                    mma_f16(o[mf][2 * vp],     pb[cb][mf][0], pb[cb][mf][1], pb[cb][mf][2], pb[cb][mf][3], vc0, vc1);
                    mma_f16(o[mf][2 * vp + 1], pb[cb][mf][0], pb[cb][mf][1], pb[cb][mf][2], pb[cb][mf][3], vc2, vc3);
                }
                if (flat < 15) { vc0 = vn0; vc1 = vn1; vc2 = vn2; vc3 = vn3; }
            }
        }
        #undef K_ADDR
        #undef V_ADDR

        #pragma unroll
        for (int mf = 0; mf < 2; mf++) {
            float2 f0 = __half22float2(*(__half2*)&lh[mf][0]);
            float2 f1 = __half22float2(*(__half2*)&lh[mf][1]);
            lacc[mf][0] += f0.x + f0.y;
            lacc[mf][1] += f1.x + f1.y;
        }
    }

    #pragma unroll
    for (int mf = 0; mf < 2; mf++)
        #pragma unroll
        for (int i = 0; i < 2; i++) {
            lacc[mf][i] += __shfl_xor_sync(0xffffffffu, lacc[mf][i], 1);
            lacc[mf][i] += __shfl_xor_sync(0xffffffffu, lacc[mf][i], 2);
        }
    #pragma unroll
    for (int mf = 0; mf < 2; mf++) {
        float inv0 = 1.0f / lacc[mf][0];
        float inv1 = 1.0f / lacc[mf][1];
        int r0 = q0 + warp * 32 + mf * 16 + (lane >> 2);
        int r1 = r0 + 8;
        size_t base0 = ((size_t)b * SS + r0) * DD + h * WW + 2 * (lane & 3);
        size_t base1 = ((size_t)b * SS + r1) * DD + h * WW + 2 * (lane & 3);
        #pragma unroll
        for (int nt = 0; nt < 8; nt++) {
            *(float2*)&out[base0 + nt * 8] = make_float2(o[mf][nt][0] * inv0, o[mf][nt][1] * inv0);
            *(float2*)&out[base1 + nt * 8] = make_float2(o[mf][nt][2] * inv1, o[mf][nt][3] * inv1);
        }
    }
}

// ===========================================================================
// Launch
// ===========================================================================
extern "C" void kernel_launch(void* const* d_in, const int* in_sizes, int n_in,
                              void* d_out, int out_size)
{
    const float* x  = (const float*)d_in[0];
    const int* mask = (const int*)d_in[1];
    const float* Wq = (const float*)d_in[2];
    const float* bq = (const float*)d_in[3];
    const float* Wk = (const float*)d_in[4];
    const float* bk = (const float*)d_in[5];
    const float* Wv = (const float*)d_in[6];
    const float* bv = (const float*)d_in[7];
    float* out = (float*)d_out;

    cudaFuncSetAttribute(qkv_mma_kernel, cudaFuncAttributeMaxDynamicSharedMemorySize, QSMEM);
    cudaFuncSetAttribute(attn_f16_kernel, cudaFuncAttributeMaxDynamicSharedMemorySize, ASMEM);

    split_x_kernel<<<GM * GK / 1024, 256>>>(x);
    dim3 gw(GK * GK / 1024, 3);
    conv_w_kernel<<<gw, 256>>>(Wq, Wk, Wv);

    dim3 g1(GN / 128, GM / 128);   // (24, 64)
    qkv_mma_kernel<<<g1, 128, QSMEM>>>(bq, bk, bv);

    dim3 g2(SS / 128, BB * HH);    // (16, 64)
    attn_f16_kernel<<<g2, 128, ASMEM>>>(mask, out);
}

// round 13
// speedup vs baseline: 1.1030x; 1.0171x over previous
#include <cuda_runtime.h>
#include <cuda_fp16.h>
#include <cstdint>

// Problem dims
#define BB 4
#define SS 2048
#define DD 1024
#define HH 16
#define WW 64
#define NEL (BB*HH*SS*WW)
#define GM 8192
#define GK 1024
#define GN 3072

#define NSM 148
#define PERSIST (2 * NSM)   // 296 CTAs, 2 per SM

// fp16 scratch. g_qh is pre-scaled by 0.125*log2(e).
__device__ __half g_qh[NEL];
__device__ __half g_kh[NEL];
__device__ __half g_vh[NEL];
__device__ __half g_xh[GM*GK];
__device__ __half g_w16[3*GK*GK];   // W in native [mat][k][n] layout, fp16

// ===========================================================================
// helpers
// ===========================================================================
__device__ __forceinline__ uint32_t smem_u32(const void* p) {
    uint32_t a;
    asm("{ .reg .u64 t; cvta.to.shared.u64 t, %1; cvt.u32.u64 %0, t; }" : "=r"(a) : "l"(p));
    return a;
}
__device__ __forceinline__ void ldsm4(uint32_t& r0, uint32_t& r1, uint32_t& r2, uint32_t& r3, uint32_t a) {
    asm volatile("ldmatrix.sync.aligned.m8n8.x4.shared.b16 {%0,%1,%2,%3}, [%4];"
                 : "=r"(r0), "=r"(r1), "=r"(r2), "=r"(r3) : "r"(a));
}
__device__ __forceinline__ void ldsm4t(uint32_t& r0, uint32_t& r1, uint32_t& r2, uint32_t& r3, uint32_t a) {
    asm volatile("ldmatrix.sync.aligned.m8n8.x4.trans.shared.b16 {%0,%1,%2,%3}, [%4];"
                 : "=r"(r0), "=r"(r1), "=r"(r2), "=r"(r3) : "r"(a));
}
__device__ __forceinline__ void mma_f16(float* c, uint32_t a0, uint32_t a1, uint32_t a2, uint32_t a3,
                                        uint32_t b0, uint32_t b1) {
    asm volatile("mma.sync.aligned.m16n8k16.row.col.f32.f16.f16.f32 "
                 "{%0,%1,%2,%3},{%4,%5,%6,%7},{%8,%9},{%0,%1,%2,%3};"
                 : "+f"(c[0]), "+f"(c[1]), "+f"(c[2]), "+f"(c[3])
                 : "r"(a0), "r"(a1), "r"(a2), "r"(a3), "r"(b0), "r"(b1));
}
__device__ __forceinline__ void cpa16(uint32_t s, const void* g) {
    asm volatile("cp.async.cg.shared.global [%0], [%1], 16;" :: "r"(s), "l"(g));
}
#define CPA_COMMIT() asm volatile("cp.async.commit_group;" ::: "memory")
#define CPA_WAIT(n)  asm volatile("cp.async.wait_group %0;" :: "n"(n) : "memory")

__device__ __forceinline__ uint32_t packh2(float a, float b) {
    __half2 h = __floats2half2_rn(a, b);
    return *reinterpret_cast<uint32_t*>(&h);
}
__device__ __forceinline__ uint32_t hadd2(uint32_t a, uint32_t b) {
    uint32_t d; asm("add.f16x2 %0, %1, %2;" : "=r"(d) : "r"(a), "r"(b)); return d;
}
__device__ __forceinline__ uint32_t ex2h2(uint32_t a) {
    uint32_t d; asm("ex2.approx.f16x2 %0, %1;" : "=r"(d) : "r"(a)); return d;
}

extern __shared__ char dyn_sm[];

// ===========================================================================
// Pre-pass 1: x -> fp16
// ===========================================================================
__global__ __launch_bounds__(256) void split_x_kernel(const float* __restrict__ x)
{
    int i = blockIdx.x * 256 + threadIdx.x;
    float4 v = ((const float4*)x)[i];
    uint2 hi = make_uint2(packh2(v.x, v.y), packh2(v.z, v.w));
    *(uint2*)&g_xh[(size_t)i * 4] = hi;
}

// ===========================================================================
// Pre-pass 2: W -> fp16, native layout
// ===========================================================================
__global__ __launch_bounds__(256) void conv_w_kernel(
    const float* __restrict__ Wq, const float* __restrict__ Wk, const float* __restrict__ Wv)
{
    const int mat = blockIdx.y;
    const float* W = (mat == 0) ? Wq : (mat == 1) ? Wk : Wv;
    int i = blockIdx.x * 256 + threadIdx.x;
    float4 v = ((const float4*)W)[i];
    uint2 hv = make_uint2(packh2(v.x, v.y), packh2(v.z, v.w));
    *(uint2*)&g_w16[(size_t)mat * GK * GK + (size_t)i * 4] = hv;
}

// ===========================================================================
// QKV GEMM fp16, PERSISTENT: 296 CTAs loop over 1536 (n-blk, m-blk) items.
// Per item: CTA 128x128, 4 warps of 64x64, K-tile 64, 3-stage cp.async.
// B from native [k][n] W tiles via ldsm4t.
// ===========================================================================
#define XT 18432             // 128 * 144
#define WT 17408             // 64 * 272
#define QSTAGE (XT + WT)     // 35840
#define QSMEM  (3 * QSTAGE)  // 107520
#define QITEMS ((GN / 128) * (GM / 128))   // 1536

__global__ __launch_bounds__(128, 2) void qkv_mma_kernel(
    const float* __restrict__ bq, const float* __restrict__ bk, const float* __restrict__ bv)
{
    const uint32_t sb = smem_u32(dyn_sm);
    const int tid = threadIdx.x;
    const int lane = tid & 31, warp = tid >> 5;
    const int warp_m = warp & 1, warp_n = warp >> 1;
    const int mbase_r = warp_m * 64 + (lane & 7) + ((lane & 8) ? 8 : 0);

    for (int item = blockIdx.x; item < QITEMS; item += PERSIST) {
        const int nblk = item % (GN / 128);
        const int m0 = (item / (GN / 128)) * 128;
        const int mat = nblk >> 3;
        const int nmat0 = (nblk & 7) * 128;

        const __half* xsrc = g_xh + (size_t)m0 * GK;
        const __half* wsrc = g_w16 + (size_t)mat * GK * GK + nmat0;

        __syncthreads();   // smem buffers free from previous item

        // prologue: stages 0 and 1
        #pragma unroll
        for (int st = 0; st < 2; st++) {
            #pragma unroll
            for (int l = 0; l < 16; l++) {
                int i = tid + l * 128;
                if (i < 1024) {
                    int row = i >> 3, j = i & 7;
                    cpa16(sb + st * QSTAGE + row * 144 + j * 16,
                          xsrc + (size_t)row * GK + st * 64 + j * 8);
                } else {
                    int idx = i - 1024;
                    int kr = idx >> 4, j = idx & 15;
                    cpa16(sb + st * QSTAGE + XT + kr * 272 + j * 16,
                          wsrc + (size_t)(st * 64 + kr) * GK + j * 8);
                }
            }
            CPA_COMMIT();
        }

        float acc[4][8][4];
        #pragma unroll
        for (int a = 0; a < 4; a++)
            #pragma unroll
            for (int c = 0; c < 8; c++)
                #pragma unroll
                for (int d = 0; d < 4; d++) acc[a][c][d] = 0.f;

        int buf = 0;
        for (int kt = 0; kt < GK / 64; kt++) {
            if (kt < GK / 64 - 1) { CPA_WAIT(1); } else { CPA_WAIT(0); }
            __syncthreads();

            if (kt + 2 < GK / 64) {
                int ib = (kt + 2) % 3;
                int k0 = (kt + 2) * 64;
                #pragma unroll
                for (int l = 0; l < 16; l++) {
                    int i = tid + l * 128;
                    if (i < 1024) {
                        int row = i >> 3, j = i & 7;
                        cpa16(sb + ib * QSTAGE + row * 144 + j * 16,
                              xsrc + (size_t)row * GK + k0 + j * 8);
                    } else {
                        int idx = i - 1024;
                        int kr = idx >> 4, j = idx & 15;
                        cpa16(sb + ib * QSTAGE + XT + kr * 272 + j * 16,
                              wsrc + (size_t)(k0 + kr) * GK + j * 8);
                    }
                }
                CPA_COMMIT();
            }

            const uint32_t ab = sb + buf * QSTAGE;
            buf = (buf + 1) % 3;

            #define QB_ADDR(kk_, nf_) (ab + XT \
                + (uint32_t)((kk_) * 16 + (lane & 7) + ((lane & 8) ? 8 : 0)) * 272 \
                + (uint32_t)(warp_n * 64 + (nf_) * 16 + ((lane & 16) ? 8 : 0)) * 2)

            uint32_t bcur0, bcur1, bcur2, bcur3;
            ldsm4t(bcur0, bcur1, bcur2, bcur3, QB_ADDR(0, 0));

            #pragma unroll
            for (int kk = 0; kk < 4; kk++) {
                const uint32_t acol = (uint32_t)(kk * 16 + ((lane & 16) ? 8 : 0)) * 2;
                uint32_t ah[4][4];
                #pragma unroll
                for (int mf = 0; mf < 4; mf++) {
                    uint32_t addr = ab + (uint32_t)(mbase_r + mf * 16) * 144 + acol;
                    ldsm4(ah[mf][0], ah[mf][1], ah[mf][2], ah[mf][3], addr);
                }
                #pragma unroll
                for (int nf = 0; nf < 4; nf++) {
                    uint32_t bn0, bn1, bn2, bn3;
                    int flat = kk * 4 + nf;
                    if (flat < 15) {
                        int nk = (flat + 1) >> 2, nn = (flat + 1) & 3;
                        ldsm4t(bn0, bn1, bn2, bn3, QB_ADDR(nk, nn));
                    }
                    #pragma unroll
                    for (int mf = 0; mf < 4; mf++) {
                        mma_f16(acc[mf][2*nf],   ah[mf][0], ah[mf][1], ah[mf][2], ah[mf][3], bcur0, bcur1);
                        mma_f16(acc[mf][2*nf+1], ah[mf][0], ah[mf][1], ah[mf][2], ah[mf][3], bcur2, bcur3);
                    }
                    if (flat < 15) { bcur0 = bn0; bcur1 = bn1; bcur2 = bn2; bcur3 = bn3; }
                }
            }
            #undef QB_ADDR
        }

        // epilogue
        const float* biasp = (mat == 0) ? bq : (mat == 1) ? bk : bv;
        __half* ohp = (mat == 0) ? g_qh : (mat == 1) ? g_kh : g_vh;
        const float qscale = (mat == 0) ? 0.125f * 1.44269504f : 1.0f;

        #pragma unroll
        for (int mf = 0; mf < 4; mf++) {
            #pragma unroll
            for (int hf = 0; hf < 2; hf++) {
                int gm = m0 + warp_m * 64 + mf * 16 + (lane >> 2) + hf * 8;
                int bb = gm >> 11, s = gm & 2047;
                #pragma unroll
                for (int nf = 0; nf < 8; nf++) {
                    int cn = nmat0 + warp_n * 64 + nf * 8 + 2 * (lane & 3);
                    float2 bv2 = *(const float2*)&biasp[cn];
                    float v0 = (acc[mf][nf][hf * 2 + 0] + bv2.x) * qscale;
                    float v1 = (acc[mf][nf][hf * 2 + 1] + bv2.y) * qscale;
                    int hh = cn >> 6, w = cn & 63;
                    size_t idx = (((size_t)bb * HH + hh) * SS + s) * WW + w;
                    *(uint32_t*)&ohp[idx] = packh2(v0, v1);
                }
            }
        }
    }
}

// ===========================================================================
// fp16 flash attention, PERSISTENT: 296 CTAs loop over 1024 (q-tile, bh)
// items. Per item identical to R12 kernel.
// ===========================================================================
#define ASTG 9216                       // one 64x144B tile
#define SO_QQ   (6 * ASTG)              // 55296 (3 stages x {K,V})
#define SO_BIAS (SO_QQ + 18432)         // 73728
#define ASMEM   (SO_BIAS + (SS/2) * 4)  // 77824
#define AITEMS ((SS / 128) * BB * HH)   // 1024

__global__ __launch_bounds__(128, 2) void attn_f16_kernel(
    const int* __restrict__ mask, float* __restrict__ out)
{
    const uint32_t sb = smem_u32(dyn_sm);
    uint32_t* biash = (uint32_t*)(dyn_sm + SO_BIAS);
    const int tid = threadIdx.x;
    const int lane = tid & 31, warp = tid >> 5;

    // Phase-stagger wave-slot-B CTAs (timing only).
    if ((blockIdx.x / NSM) & 1) {
        long long t0 = clock64();
        while (clock64() - t0 < 600) { }
    }

    for (int item = blockIdx.x; item < AITEMS; item += PERSIST) {
        const int q0 = (item & 15) * 128;
        const int bh = item >> 4;
        const int b = bh / HH, h = bh % HH;
        const size_t bhoff = (size_t)bh * SS * WW;

        __syncthreads();   // smem free from previous item

        for (int i = tid; i < SS / 2; i += 128) {
            int mv0 = mask[b * SS + 2 * i];
            int mv1 = mask[b * SS + 2 * i + 1];
            biash[i] = packh2(mv0 ? 0.f : -30000.f, mv1 ? 0.f : -30000.f);
        }

        #pragma unroll
        for (int l = 0; l < 8; l++) {
            int i = tid + l * 128;
            int r = i >> 3, j = i & 7;
            cpa16(sb + SO_QQ + r * 144 + j * 16, g_qh + bhoff + (size_t)(q0 + r) * WW + j * 8);
        }
        CPA_COMMIT();

        #pragma unroll
        for (int st = 0; st < 2; st++) {
            #pragma unroll
            for (int l = 0; l < 8; l++) {
                int i = tid + l * 128;
                int sel = i >> 9, rem = i & 511;
                int r = rem >> 3, j = rem & 7;
                const __half* src = (sel ? g_vh : g_kh) + bhoff + (size_t)(st * 64 + r) * WW + j * 8;
                cpa16(sb + st * 2 * ASTG + sel * ASTG + r * 144 + j * 16, src);
            }
            CPA_COMMIT();
        }

        CPA_WAIT(2);
        __syncthreads();

        uint32_t qh[2][4][4];
        #pragma unroll
        for (int mf = 0; mf < 2; mf++) {
            int row = warp * 32 + mf * 16 + (lane & 7) + ((lane & 8) ? 8 : 0);
            #pragma unroll
            for (int ks = 0; ks < 4; ks++) {
                int col = ks * 16 + ((lane & 16) ? 8 : 0);
                uint32_t a = sb + SO_QQ + row * 144 + col * 2;
                ldsm4(qh[mf][ks][0], qh[mf][ks][1], qh[mf][ks][2], qh[mf][ks][3], a);
            }
        }

        float lacc[2][2] = {{0.f, 0.f}, {0.f, 0.f}};
        float o[2][8][4];
        #pragma unroll
        for (int mf = 0; mf < 2; mf++)
            #pragma unroll
            for (int i = 0; i < 8; i++)
                #pragma unroll
                for (int j = 0; j < 4; j++) o[mf][i][j] = 0.f;

        int buf = 0;
        for (int kt = 0; kt < SS / 64; kt++) {
            if (kt < SS / 64 - 1) { CPA_WAIT(1); } else { CPA_WAIT(0); }
            __syncthreads();

            if (kt + 2 < SS / 64) {
                int ib = (kt + 2) % 3;
                size_t srow = (size_t)(kt + 2) * 64;
                #pragma unroll
                for (int l = 0; l < 8; l++) {
                    int i = tid + l * 128;
                    int sel = i >> 9, rem = i & 511;
                    int r = rem >> 3, j = rem & 7;
                    const __half* src = (sel ? g_vh : g_kh) + bhoff + (srow + r) * WW + j * 8;
                    cpa16(sb + ib * 2 * ASTG + sel * ASTG + r * 144 + j * 16, src);
                }
                CPA_COMMIT();
            }

            const uint32_t kb = sb + buf * 2 * ASTG;
            buf = (buf + 1) % 3;

            uint32_t bih[8];
            #pragma unroll
            for (int nt = 0; nt < 8; nt++)
                bih[nt] = biash[(kt * 64 + nt * 8 + 2 * (lane & 3)) >> 1];

            #define K_ADDR(ks_, np_) (kb + (uint32_t)((np_) * 16 + (lane & 7) + ((lane & 16) ? 8 : 0)) * 144 \
                                      + (uint32_t)((ks_) * 16 + ((lane & 8) ? 8 : 0)) * 2)
            #define V_ADDR(ks_, vp_) (kb + ASTG + (uint32_t)((ks_) * 16 + (lane & 7) + ((lane & 8) ? 8 : 0)) * 144 \
                                      + (uint32_t)((vp_) * 16 + ((lane & 16) ? 8 : 0)) * 2)

            float s[2][8][4];
            #pragma unroll
            for (int mf = 0; mf < 2; mf++)
                #pragma unroll
                for (int i = 0; i < 8; i++)
                    #pragma unroll
                    for (int j = 0; j < 4; j++) s[mf][i][j] = 0.f;

            {
                uint32_t kc0, kc1, kc2, kc3;
                ldsm4(kc0, kc1, kc2, kc3, K_ADDR(0, 0));
                #pragma unroll
                for (int it = 0; it < 16; it++) {
                    int ks = it >> 2, np = it & 3;
                    uint32_t kn0, kn1, kn2, kn3;
                    if (it < 15) {
                        int nk = (it + 1) >> 2, nn = (it + 1) & 3;
                        ldsm4(kn0, kn1, kn2, kn3, K_ADDR(nk, nn));
                    }
                    #pragma unroll
                    for (int mf = 0; mf < 2; mf++) {
                        mma_f16(s[mf][2 * np],     qh[mf][ks][0], qh[mf][ks][1], qh[mf][ks][2], qh[mf][ks][3], kc0, kc1);
                        mma_f16(s[mf][2 * np + 1], qh[mf][ks][0], qh[mf][ks][1], qh[mf][ks][2], qh[mf][ks][3], kc2, kc3);
                    }
                    if (it < 15) { kc0 = kn0; kc1 = kn1; kc2 = kn2; kc3 = kn3; }
                }
            }

            uint32_t lh[2][2] = {{0u, 0u}, {0u, 0u}};
            uint32_t pb[2][2][4];

            #pragma unroll
            for (int t = 0; t < 2; t++) {
                #pragma unroll
                for (int mf = 0; mf < 2; mf++) {
                    uint32_t a0 = ex2h2(hadd2(packh2(s[mf][t][0], s[mf][t][1]), bih[t]));
                    uint32_t a1 = ex2h2(hadd2(packh2(s[mf][t][2], s[mf][t][3]), bih[t]));
                    pb[0][mf][2 * t]     = a0;
                    pb[0][mf][2 * t + 1] = a1;
                    lh[mf][0] = hadd2(lh[mf][0], a0);
                    lh[mf][1] = hadd2(lh[mf][1], a1);
                }
            }

            uint32_t vc0, vc1, vc2, vc3;
            ldsm4t(vc0, vc1, vc2, vc3, V_ADDR(0, 0));

            #pragma unroll
            for (int ks = 0; ks < 4; ks++) {
                int cb = ks & 1;
                if (ks < 3) {
                    #pragma unroll
                    for (int t = 0; t < 2; t++) {
                        int nt = 2 * (ks + 1) + t;
                        #pragma unroll
                        for (int mf = 0; mf < 2; mf++) {
                            uint32_t a0 = ex2h2(hadd2(packh2(s[mf][nt][0], s[mf][nt][1]), bih[nt]));
                            uint32_t a1 = ex2h2(hadd2(packh2(s[mf][nt][2], s[mf][nt][3]), bih[nt]));
                            pb[cb ^ 1][mf][2 * t]     = a0;
                            pb[cb ^ 1][mf][2 * t + 1] = a1;
                            lh[mf][0] = hadd2(lh[mf][0], a0);
                            lh[mf][1] = hadd2(lh[mf][1], a1);
                        }
                    }
                }
                #pragma unroll
                for (int vp = 0; vp < 4; vp++) {
                    uint32_t vn0, vn1, vn2, vn3;
                    int flat = ks * 4 + vp;
                    if (flat < 15) {
                        int nk = (flat + 1) >> 2, nv = (flat + 1) & 3;
                        ldsm4t(vn0, vn1, vn2, vn3, V_ADDR(nk, nv));
                    }
                    #pragma unroll
                    for (int mf = 0; mf < 2; mf++) {
                        mma_f16(o[mf][2 * vp],     pb[cb][mf][0], pb[cb][mf][1], pb[cb][mf][2], pb[cb][mf][3], vc0, vc1);
                        mma_f16(o[mf][2 * vp + 1], pb[cb][mf][0], pb[cb][mf][1], pb[cb][mf][2], pb[cb][mf][3], vc2, vc3);
                    }
                    if (flat < 15) { vc0 = vn0; vc1 = vn1; vc2 = vn2; vc3 = vn3; }
                }
            }
            #undef K_ADDR
            #undef V_ADDR

            #pragma unroll
            for (int mf = 0; mf < 2; mf++) {
                float2 f0 = __half22float2(*(__half2*)&lh[mf][0]);
                float2 f1 = __half22float2(*(__half2*)&lh[mf][1]);
                lacc[mf][0] += f0.x + f0.y;
                lacc[mf][1] += f1.x + f1.y;
            }
        }

        #pragma unroll
        for (int mf = 0; mf < 2; mf++)
            #pragma unroll
            for (int i = 0; i < 2; i++) {
                lacc[mf][i] += __shfl_xor_sync(0xffffffffu, lacc[mf][i], 1);
                lacc[mf][i] += __shfl_xor_sync(0xffffffffu, lacc[mf][i], 2);
            }
        #pragma unroll
        for (int mf = 0; mf < 2; mf++) {
            float inv0 = 1.0f / lacc[mf][0];
            float inv1 = 1.0f / lacc[mf][1];
            int r0 = q0 + warp * 32 + mf * 16 + (lane >> 2);
            int r1 = r0 + 8;
            size_t base0 = ((size_t)b * SS + r0) * DD + h * WW + 2 * (lane & 3);
            size_t base1 = ((size_t)b * SS + r1) * DD + h * WW + 2 * (lane & 3);
            #pragma unroll
            for (int nt = 0; nt < 8; nt++) {
                *(float2*)&out[base0 + nt * 8] = make_float2(o[mf][nt][0] * inv0, o[mf][nt][1] * inv0);
                *(float2*)&out[base1 + nt * 8] = make_float2(o[mf][nt][2] * inv1, o[mf][nt][3] * inv1);
            }
        }
    }
}

// ===========================================================================
// Launch
// ===========================================================================
extern "C" void kernel_launch(void* const* d_in, const int* in_sizes, int n_in,
                              void* d_out, int out_size)
{
    const float* x  = (const float*)d_in[0];
    const int* mask = (const int*)d_in[1];
    const float* Wq = (const float*)d_in[2];
    const float* bq = (const float*)d_in[3];
    const float* Wk = (const float*)d_in[4];
    const float* bk = (const float*)d_in[5];
    const float* Wv = (const float*)d_in[6];
    const float* bv = (const float*)d_in[7];
    float* out = (float*)d_out;

    cudaFuncSetAttribute(qkv_mma_kernel, cudaFuncAttributeMaxDynamicSharedMemorySize, QSMEM);
    cudaFuncSetAttribute(attn_f16_kernel, cudaFuncAttributeMaxDynamicSharedMemorySize, ASMEM);

    split_x_kernel<<<GM * GK / 1024, 256>>>(x);
    dim3 gw(GK * GK / 1024, 3);
    conv_w_kernel<<<gw, 256>>>(Wq, Wk, Wv);

    qkv_mma_kernel<<<PERSIST, 128, QSMEM>>>(bq, bk, bv);
    attn_f16_kernel<<<PERSIST, 128, ASMEM>>>(mask, out);
}